// round 3
// baseline (speedup 1.0000x reference)
#include <cuda_runtime.h>
#include <math.h>

#define NPTS   262144
#define NPART  24
#define CC     24
#define RR     128
#define TILE   128
#define THREADS 256

// Channel-last triplanes: [p][k][y][x][c], 24*3*128*128*24 floats = 113 MB
__device__ float g_planes[(size_t)NPART * 3 * RR * RR * CC];
// Effective bias for the Wl layer (latent branch folded in)
__device__ float g_bl_eff[128];

// ---------------------------------------------------------------------------
// Prepass 1: transpose triplanes (NPART,72,128,128) -> [p][k][y][x][c]
// ---------------------------------------------------------------------------
__global__ void transpose_planes(const float* __restrict__ tp) {
    __shared__ float tile[CC][136];
    int y  = blockIdx.x;   // 0..127
    int pk = blockIdx.y;   // 0..71
    int p = pk / 3, k = pk % 3;
    int t = threadIdx.x;

    for (int it = t; it < CC * RR; it += THREADS) {
        int c = it >> 7;          // 0..23
        int x = it & 127;
        tile[c][x] = tp[(((size_t)(p * 72 + k * 24 + c) * RR + y) * RR) + x];
    }
    __syncthreads();
    float* dst = g_planes + (((size_t)(p * 3 + k) * RR + y) * RR) * CC;
    for (int it = t; it < CC * RR; it += THREADS) {
        int x = it / 24;
        int c = it - x * 24;
        dst[it] = tile[c][x];     // dst linear index = x*24 + c == it
    }
}

// ---------------------------------------------------------------------------
// Prepass 2: bl_eff[j] = bl[j] + sum_l Wl[j][128+l] * nf_latent[ind][l]
// ---------------------------------------------------------------------------
__global__ void prep_bleff(const float* __restrict__ Wl,
                           const float* __restrict__ bl,
                           const float* __restrict__ nf_latent,
                           const int* __restrict__ ind) {
    int j = threadIdx.x;  // 128 threads
    const float* L = nf_latent + (size_t)ind[0] * 128;
    float s = bl[j];
    #pragma unroll 4
    for (int l = 0; l < 128; ++l) s += Wl[j * 256 + 128 + l] * L[l];
    g_bl_eff[j] = s;
}

// ---------------------------------------------------------------------------
// Fused MLP layer: actout[OUT][128] = act(W @ actin[IN][128] + bias)
// ---------------------------------------------------------------------------
template<int IN, int OUT, bool RELU>
__device__ __forceinline__ void layer(const float* __restrict__ Wg, int wstride,
                                      const float* __restrict__ bias,
                                      const float* actin, float* actout,
                                      float* wbuf, int t) {
    const int WS = OUT + 4;
    for (int idx = t; idx < IN * OUT; idx += THREADS) {
        int j = idx / IN;
        int i = idx - j * IN;
        wbuf[i * WS + j] = __ldg(Wg + j * wstride + i);
    }
    __syncthreads();

    const int JT = OUT / 8;           // 16 (OUT=128) or 8 (OUT=64)
    int a  = t & 31;                  // point group: pts 4a..4a+3
    int b  = t >> 5;                  // output group (constant within warp)
    int j0 = b * JT;

    float acc[JT][4];
    #pragma unroll
    for (int j = 0; j < JT; ++j)
        #pragma unroll
        for (int u = 0; u < 4; ++u) acc[j][u] = 0.f;

    #pragma unroll 2
    for (int i = 0; i < IN; ++i) {
        float4 av = *(const float4*)(actin + i * TILE + a * 4);
        #pragma unroll
        for (int jj = 0; jj < JT / 4; ++jj) {
            float4 wv = *(const float4*)(wbuf + i * WS + j0 + jj * 4);
            float wq0 = wv.x, wq1 = wv.y, wq2 = wv.z, wq3 = wv.w;
            acc[jj*4+0][0] += wq0*av.x; acc[jj*4+0][1] += wq0*av.y; acc[jj*4+0][2] += wq0*av.z; acc[jj*4+0][3] += wq0*av.w;
            acc[jj*4+1][0] += wq1*av.x; acc[jj*4+1][1] += wq1*av.y; acc[jj*4+1][2] += wq1*av.z; acc[jj*4+1][3] += wq1*av.w;
            acc[jj*4+2][0] += wq2*av.x; acc[jj*4+2][1] += wq2*av.y; acc[jj*4+2][2] += wq2*av.z; acc[jj*4+2][3] += wq2*av.w;
            acc[jj*4+3][0] += wq3*av.x; acc[jj*4+3][1] += wq3*av.y; acc[jj*4+3][2] += wq3*av.z; acc[jj*4+3][3] += wq3*av.w;
        }
    }

    #pragma unroll
    for (int j = 0; j < JT; ++j) {
        float bj = __ldg(bias + j0 + j);
        float4 o;
        o.x = acc[j][0] + bj; o.y = acc[j][1] + bj;
        o.z = acc[j][2] + bj; o.w = acc[j][3] + bj;
        if (RELU) {
            o.x = fmaxf(o.x, 0.f); o.y = fmaxf(o.y, 0.f);
            o.z = fmaxf(o.z, 0.f); o.w = fmaxf(o.w, 0.f);
        }
        *(float4*)(actout + (j0 + j) * TILE + a * 4) = o;
    }
    __syncthreads();
}

// ---------------------------------------------------------------------------
// Main fused kernel: one block = 128 points, full pipeline in SMEM.
// ---------------------------------------------------------------------------
__global__ void __launch_bounds__(THREADS, 1)
tpose_kernel(const float* __restrict__ part_coord,
             const float* __restrict__ viewdir,
             const float* __restrict__ part_bounds,
             const float* __restrict__ W1, const float* __restrict__ b1,
             const float* __restrict__ W2, const float* __restrict__ b2,
             const float* __restrict__ Wa, const float* __restrict__ ba,
             const float* __restrict__ Wf, const float* __restrict__ bf,
             const float* __restrict__ Wl,
             const float* __restrict__ Wv, const float* __restrict__ bv,
             const float* __restrict__ Wr, const float* __restrict__ br,
             const int* __restrict__ part_idx,
             float* __restrict__ out) {
    extern __shared__ float smem[];
    float* bufA = smem;                    // 156*128 rows (feat/net2/feat2+vemb)
    float* bufB = bufA + 156 * TILE;       // 128*128
    float* wbuf = bufB + 128 * TILE;       // max 128*132 = 16896
    int*   sO00 = (int*)(wbuf + 16896);    // 3*128 per-texel offsets
    int*   sO01 = sO00 + 3 * TILE;
    int*   sO10 = sO01 + 3 * TILE;
    int*   sO11 = sO10 + 3 * TILE;
    float* sWx  = (float*)(sO11 + 3 * TILE);
    float* sWy  = sWx + 3 * TILE;

    int t = threadIdx.x;
    int tile0 = blockIdx.x * TILE;

    // --- per-point sampling params ---
    if (t < TILE) {
        int n = tile0 + t;
        float P[3] = { part_coord[3*n], part_coord[3*n+1], part_coord[3*n+2] };
        int p = part_idx[n];
        // part_bounds layout: (NPART, 2, 3) -> per part: [mn_x,mn_y,mn_z, mx_x,mx_y,mx_z]
        const float* bb = part_bounds + p * 6;
        float g[3];
        #pragma unroll
        for (int d = 0; d < 3; ++d) {
            float mn = bb[d], mx = bb[3 + d];
            float c = 0.5f * (mn + mx), h = 0.5f * (mx - mn);
            g[d] = (P[d] - c) / h;
        }
        const int ka[3] = {0, 0, 1};
        const int kb[3] = {1, 2, 2};
        #pragma unroll
        for (int k = 0; k < 3; ++k) {
            float u = g[ka[k]], v = g[kb[k]];
            float px = fminf(fmaxf((u + 1.f) * 0.5f * (RR - 1), 0.f), (float)(RR - 1));
            float py = fminf(fmaxf((v + 1.f) * 0.5f * (RR - 1), 0.f), (float)(RR - 1));
            float x0 = floorf(px), y0 = floorf(py);
            int x0i = (int)x0, y0i = (int)y0;
            int x1i = min(x0i + 1, RR - 1), y1i = min(y0i + 1, RR - 1);
            int rb = (p * 3 + k) * RR;
            sO00[k*TILE + t] = ((rb + y0i) * RR + x0i) * CC;
            sO01[k*TILE + t] = ((rb + y0i) * RR + x1i) * CC;
            sO10[k*TILE + t] = ((rb + y1i) * RR + x0i) * CC;
            sO11[k*TILE + t] = ((rb + y1i) * RR + x1i) * CC;
            sWx[k*TILE + t] = px - x0;
            sWy[k*TILE + t] = py - y0;
        }
    }
    __syncthreads();

    // --- triplane gather: lanes 0..23 = channels (contiguous 96B reads) ---
    {
        int w = t >> 5, c = t & 31;
        if (c < CC) {
            for (int idx = w; idx < 3 * TILE; idx += 8) {
                int o00 = sO00[idx], o01 = sO01[idx], o10 = sO10[idx], o11 = sO11[idx];
                float wx = sWx[idx], wy = sWy[idx];
                float f00 = g_planes[o00 + c], f01 = g_planes[o01 + c];
                float f10 = g_planes[o10 + c], f11 = g_planes[o11 + c];
                float f = f00 * (1.f - wx) * (1.f - wy) + f01 * wx * (1.f - wy)
                        + f10 * (1.f - wx) * wy        + f11 * wx * wy;
                int k = idx >> 7, pt = idx & 127;
                bufA[(k * CC + c) * TILE + pt] = f;
            }
        }
    }
    // layer() stages weights then syncs -> gather writes are ordered before GEMM reads.

    layer<72, 128, true >(W1, 72,  b1,       bufA, bufB, wbuf, t);  // net1
    layer<128,128, true >(W2, 128, b2,       bufB, bufA, wbuf, t);  // net2 -> bufA

    // alpha = Wa @ net2 + ba
    if (t < TILE) {
        float s = __ldg(ba);
        #pragma unroll 4
        for (int i = 0; i < 128; ++i) s += __ldg(Wa + i) * bufA[i * TILE + t];
        out[tile0 + t] = s;
    }

    layer<128,128, false>(Wf, 128, bf,       bufA, bufB, wbuf, t);  // features1
    layer<128,128, false>(Wl, 256, g_bl_eff, bufB, bufA, wbuf, t);  // features2 (latent folded)

    // view posenc -> bufA rows 128..154
    if (t < TILE) {
        int n = tile0 + t;
        float dd[3] = { viewdir[3*n], viewdir[3*n+1], viewdir[3*n+2] };
        bufA[128 * TILE + t] = dd[0];
        bufA[129 * TILE + t] = dd[1];
        bufA[130 * TILE + t] = dd[2];
        #pragma unroll
        for (int f = 0; f < 4; ++f) {
            float fr = (float)(1 << f);
            #pragma unroll
            for (int dim = 0; dim < 3; ++dim) {
                float ang = dd[dim] * fr;
                bufA[(131 + f * 6 + dim)     * TILE + t] = sinf(ang);
                bufA[(131 + f * 6 + 3 + dim) * TILE + t] = cosf(ang);
            }
        }
    }

    layer<155, 64, true >(Wv, 155, bv,       bufA, bufB, wbuf, t);  // h

    // rgb = Wr @ h + br  -> out layout: [alpha(N)][r(N)][g(N)][b(N)]
    if (t < TILE) {
        float s0 = __ldg(br), s1 = __ldg(br + 1), s2 = __ldg(br + 2);
        #pragma unroll 4
        for (int i = 0; i < 64; ++i) {
            float h = bufB[i * TILE + t];
            s0 += __ldg(Wr + i)       * h;
            s1 += __ldg(Wr + 64 + i)  * h;
            s2 += __ldg(Wr + 128 + i) * h;
        }
        int n = tile0 + t;
        out[NPTS + n]            = s0;
        out[NPTS + NPTS + n]     = s1;
        out[NPTS + 2 * NPTS + n] = s2;
    }
}

// ---------------------------------------------------------------------------
extern "C" void kernel_launch(void* const* d_in, const int* in_sizes, int n_in,
                              void* d_out, int out_size) {
    const float* part_coord     = (const float*)d_in[0];
    const float* viewdir        = (const float*)d_in[1];
    const float* part_bounds    = (const float*)d_in[2];
    const float* part_triplanes = (const float*)d_in[3];
    const float* nf_latent      = (const float*)d_in[4];
    const float* W1 = (const float*)d_in[5];  const float* b1 = (const float*)d_in[6];
    const float* W2 = (const float*)d_in[7];  const float* b2 = (const float*)d_in[8];
    const float* Wa = (const float*)d_in[9];  const float* ba = (const float*)d_in[10];
    const float* Wf = (const float*)d_in[11]; const float* bf = (const float*)d_in[12];
    const float* Wl = (const float*)d_in[13]; const float* bl = (const float*)d_in[14];
    const float* Wv = (const float*)d_in[15]; const float* bv = (const float*)d_in[16];
    const float* Wr = (const float*)d_in[17]; const float* br = (const float*)d_in[18];
    const int* part_idx = (const int*)d_in[19];
    const int* ind      = (const int*)d_in[20];
    float* out = (float*)d_out;

    transpose_planes<<<dim3(RR, NPART * 3), THREADS>>>(part_triplanes);
    prep_bleff<<<1, 128>>>(Wl, bl, nf_latent, ind);

    const size_t SMEM = (size_t)(156 * 128 + 128 * 128 + 16896 + 6 * 3 * 128) * 4;
    (void)cudaFuncSetAttribute(tpose_kernel,
                               cudaFuncAttributeMaxDynamicSharedMemorySize, (int)SMEM);
    tpose_kernel<<<NPTS / TILE, THREADS, SMEM>>>(
        part_coord, viewdir, part_bounds,
        W1, b1, W2, b2, Wa, ba, Wf, bf, Wl, Wv, bv, Wr, br,
        part_idx, out);
}

// round 5
// speedup vs baseline: 1.5692x; 1.5692x over previous
#include <cuda_runtime.h>
#include <math.h>
#include <stdint.h>

#define NPTS   262144
#define NPART  24
#define CC     24
#define RR     128
#define TILE   128
#define THREADS 256
#define AS     136     // activation smem stride (conflict-free for mma B loads)

// Channel-last triplanes: [p][k][y][x][c], 24*3*128*128*24 floats = 113 MB
__device__ float g_planes[(size_t)NPART * 3 * RR * RR * CC];
__device__ float g_bl_eff[128];

__device__ __forceinline__ float to_tf32(float x) {
    uint32_t y;
    asm("cvt.rna.tf32.f32 %0, %1;" : "=r"(y) : "f"(x));
    return __uint_as_float(y);
}

// ---------------------------------------------------------------------------
// Prepass 1: transpose triplanes (NPART,72,128,128) -> [p][k][y][x][c]
// ---------------------------------------------------------------------------
__global__ void transpose_planes(const float* __restrict__ tp) {
    __shared__ float tile[CC][136];
    int y  = blockIdx.x;   // 0..127
    int pk = blockIdx.y;   // 0..71
    int p = pk / 3, k = pk % 3;
    int t = threadIdx.x;

    for (int it = t; it < CC * RR; it += THREADS) {
        int c = it >> 7;
        int x = it & 127;
        tile[c][x] = tp[(((size_t)(p * 72 + k * 24 + c) * RR + y) * RR) + x];
    }
    __syncthreads();
    float* dst = g_planes + (((size_t)(p * 3 + k) * RR + y) * RR) * CC;
    for (int it = t; it < CC * RR; it += THREADS) {
        int x = it / 24;
        int c = it - x * 24;
        dst[it] = tile[c][x];
    }
}

// ---------------------------------------------------------------------------
// Prepass 2: bl_eff[j] = bl[j] + sum_l Wl[j][128+l] * nf_latent[ind][l]
// ---------------------------------------------------------------------------
__global__ void prep_bleff(const float* __restrict__ Wl,
                           const float* __restrict__ bl,
                           const float* __restrict__ nf_latent,
                           const int* __restrict__ ind) {
    int j = threadIdx.x;
    const float* L = nf_latent + (size_t)ind[0] * 128;
    float s = bl[j];
    #pragma unroll 4
    for (int l = 0; l < 128; ++l) s += Wl[j * 256 + 128 + l] * L[l];
    g_bl_eff[j] = s;
}

// ---------------------------------------------------------------------------
// tf32 tensor-core layer: actout[OUT][128] = act(W @ actin[KDIM][128] + bias)
// KDIM multiple of 8. Weights staged row-major [OUT][KDIM+pad] (tf32-rounded),
// cols >= wcols zero-filled. mma.m16n8k8, warp tile = (OUT/4) x 64.
// ---------------------------------------------------------------------------
template<int KDIM, int OUT, bool RELU>
__device__ __forceinline__ void layer_mma(const float* __restrict__ Wg, int wstride, int wcols,
                                          const float* __restrict__ bias,
                                          const float* actin, float* actout,
                                          float* wbuf, int t) {
    constexpr int WS = KDIM + ((KDIM % 32 == 0) ? 8 : 4);  // 136 / 76 / 168
    for (int idx = t; idx < OUT * KDIM; idx += THREADS) {
        int j = idx / KDIM;
        int i = idx - j * KDIM;
        float v = (i < wcols) ? __ldg(Wg + j * wstride + i) : 0.f;
        wbuf[j * WS + i] = to_tf32(v);
    }
    __syncthreads();

    const int lane = t & 31;
    const int wid  = t >> 5;
    const int arow = lane >> 2;   // 0..7
    const int acol = lane & 3;    // 0..3
    constexpr int MT = OUT / 64;  // 2 for OUT=128, 1 for OUT=64
    const int Mbase = (wid & 3) * (MT * 16);
    const int Nbase = (wid >> 2) * 64;

    float c[MT][8][4];
    #pragma unroll
    for (int mt = 0; mt < MT; ++mt)
        #pragma unroll
        for (int nt = 0; nt < 8; ++nt)
            #pragma unroll
            for (int u = 0; u < 4; ++u) c[mt][nt][u] = 0.f;

    #pragma unroll 2
    for (int k0 = 0; k0 < KDIM; k0 += 8) {
        uint32_t A[MT][4];
        #pragma unroll
        for (int mt = 0; mt < MT; ++mt) {
            const float* wb = wbuf + (Mbase + mt * 16 + arow) * WS + k0 + acol;
            A[mt][0] = __float_as_uint(wb[0]);
            A[mt][1] = __float_as_uint(wb[8 * WS]);
            A[mt][2] = __float_as_uint(wb[4]);
            A[mt][3] = __float_as_uint(wb[8 * WS + 4]);
        }
        uint32_t B[8][2];
        #pragma unroll
        for (int nt = 0; nt < 8; ++nt) {
            const float* ab = actin + (k0 + acol) * AS + Nbase + nt * 8 + arow;
            B[nt][0] = __float_as_uint(ab[0]);
            B[nt][1] = __float_as_uint(ab[4 * AS]);
        }
        #pragma unroll
        for (int mt = 0; mt < MT; ++mt)
            #pragma unroll
            for (int nt = 0; nt < 8; ++nt) {
                asm volatile(
                    "mma.sync.aligned.m16n8k8.row.col.f32.tf32.tf32.f32 "
                    "{%0,%1,%2,%3}, {%4,%5,%6,%7}, {%8,%9}, {%0,%1,%2,%3};"
                    : "+f"(c[mt][nt][0]), "+f"(c[mt][nt][1]),
                      "+f"(c[mt][nt][2]), "+f"(c[mt][nt][3])
                    : "r"(A[mt][0]), "r"(A[mt][1]), "r"(A[mt][2]), "r"(A[mt][3]),
                      "r"(B[nt][0]), "r"(B[nt][1]));
            }
    }

    #pragma unroll
    for (int mt = 0; mt < MT; ++mt) {
        int m0 = Mbase + mt * 16 + arow;
        float bv0 = __ldg(bias + m0);
        float bv1 = __ldg(bias + m0 + 8);
        #pragma unroll
        for (int nt = 0; nt < 8; ++nt) {
            int n0 = Nbase + nt * 8 + 2 * acol;
            float r0 = c[mt][nt][0] + bv0, r1 = c[mt][nt][1] + bv0;
            float r2 = c[mt][nt][2] + bv1, r3 = c[mt][nt][3] + bv1;
            if (RELU) {
                r0 = fmaxf(r0, 0.f); r1 = fmaxf(r1, 0.f);
                r2 = fmaxf(r2, 0.f); r3 = fmaxf(r3, 0.f);
            }
            actout[m0 * AS + n0]           = to_tf32(r0);
            actout[m0 * AS + n0 + 1]       = to_tf32(r1);
            actout[(m0 + 8) * AS + n0]     = to_tf32(r2);
            actout[(m0 + 8) * AS + n0 + 1] = to_tf32(r3);
        }
    }
    __syncthreads();
}

// ---------------------------------------------------------------------------
// Main fused kernel: one block = 128 points, full pipeline in SMEM.
// ---------------------------------------------------------------------------
__global__ void __launch_bounds__(THREADS, 1)
tpose_kernel(const float* __restrict__ part_coord,
             const float* __restrict__ viewdir,
             const float* __restrict__ part_bounds,
             const float* __restrict__ W1, const float* __restrict__ b1,
             const float* __restrict__ W2, const float* __restrict__ b2,
             const float* __restrict__ Wa, const float* __restrict__ ba,
             const float* __restrict__ Wf, const float* __restrict__ bf,
             const float* __restrict__ Wl,
             const float* __restrict__ Wv, const float* __restrict__ bv,
             const float* __restrict__ Wr, const float* __restrict__ br,
             const int* __restrict__ part_idx,
             float* __restrict__ out) {
    extern __shared__ float smem[];
    float* bufA = smem;                    // 160 rows x AS
    float* bufB = bufA + 160 * AS;         // 128 rows x AS
    float* wbuf = bufB + 128 * AS;         // 128*136 max; sampling scratch overlaid
    int*   sO00 = (int*)wbuf;              // 6 x 384 ints/floats = 2304 words
    int*   sO01 = sO00 + 3 * TILE;
    int*   sO10 = sO01 + 3 * TILE;
    int*   sO11 = sO10 + 3 * TILE;
    float* sWx  = (float*)(sO11 + 3 * TILE);
    float* sWy  = sWx + 3 * TILE;

    int t = threadIdx.x;
    int tile0 = blockIdx.x * TILE;

    // --- per-point sampling params ---
    if (t < TILE) {
        int n = tile0 + t;
        float P[3] = { part_coord[3*n], part_coord[3*n+1], part_coord[3*n+2] };
        int p = part_idx[n];
        // part_bounds layout (NPART,2,3): [mn_xyz, mx_xyz]
        const float* bb = part_bounds + p * 6;
        float g[3];
        #pragma unroll
        for (int d = 0; d < 3; ++d) {
            float mn = bb[d], mx = bb[3 + d];
            float c = 0.5f * (mn + mx), h = 0.5f * (mx - mn);
            g[d] = (P[d] - c) / h;
        }
        const int ka[3] = {0, 0, 1};
        const int kb[3] = {1, 2, 2};
        #pragma unroll
        for (int k = 0; k < 3; ++k) {
            float u = g[ka[k]], v = g[kb[k]];
            float px = fminf(fmaxf((u + 1.f) * 0.5f * (RR - 1), 0.f), (float)(RR - 1));
            float py = fminf(fmaxf((v + 1.f) * 0.5f * (RR - 1), 0.f), (float)(RR - 1));
            float x0 = floorf(px), y0 = floorf(py);
            int x0i = (int)x0, y0i = (int)y0;
            int x1i = min(x0i + 1, RR - 1), y1i = min(y0i + 1, RR - 1);
            int rb = (p * 3 + k) * RR;
            sO00[k*TILE + t] = ((rb + y0i) * RR + x0i) * CC;
            sO01[k*TILE + t] = ((rb + y0i) * RR + x1i) * CC;
            sO10[k*TILE + t] = ((rb + y1i) * RR + x0i) * CC;
            sO11[k*TILE + t] = ((rb + y1i) * RR + x1i) * CC;
            sWx[k*TILE + t] = px - x0;
            sWy[k*TILE + t] = py - y0;
        }
    }
    __syncthreads();

    // --- triplane gather: lanes 0..23 = channels (contiguous 96B reads) ---
    {
        int w = t >> 5, c = t & 31;
        if (c < CC) {
            for (int idx = w; idx < 3 * TILE; idx += 8) {
                int o00 = sO00[idx], o01 = sO01[idx], o10 = sO10[idx], o11 = sO11[idx];
                float wx = sWx[idx], wy = sWy[idx];
                float f00 = g_planes[o00 + c], f01 = g_planes[o01 + c];
                float f10 = g_planes[o10 + c], f11 = g_planes[o11 + c];
                float f = f00 * (1.f - wx) * (1.f - wy) + f01 * wx * (1.f - wy)
                        + f10 * (1.f - wx) * wy        + f11 * wx * wy;
                int k = idx >> 7, pt = idx & 127;
                bufA[(k * CC + c) * AS + pt] = to_tf32(f);
            }
        }
    }
    __syncthreads();   // gather (reads sO in wbuf) done before layer1 stages wbuf

    layer_mma<72, 128, true >(W1, 72,  72,  b1,       bufA, bufB, wbuf, t);  // net1
    layer_mma<128,128, true >(W2, 128, 128, b2,       bufB, bufA, wbuf, t);  // net2 -> bufA

    // alpha = Wa @ net2 + ba
    if (t < TILE) {
        float s = __ldg(ba);
        #pragma unroll 4
        for (int i = 0; i < 128; ++i) s += __ldg(Wa + i) * bufA[i * AS + t];
        out[tile0 + t] = s;
    }

    layer_mma<128,128, false>(Wf, 128, 128, bf,       bufA, bufB, wbuf, t);  // features1
    layer_mma<128,128, false>(Wl, 256, 128, g_bl_eff, bufB, bufA, wbuf, t);  // features2 (latent folded)

    // view posenc -> bufA rows 128..154, zero rows 155..159 (K padded to 160)
    if (t < TILE) {
        int n = tile0 + t;
        float dd[3] = { viewdir[3*n], viewdir[3*n+1], viewdir[3*n+2] };
        bufA[128 * AS + t] = to_tf32(dd[0]);
        bufA[129 * AS + t] = to_tf32(dd[1]);
        bufA[130 * AS + t] = to_tf32(dd[2]);
        #pragma unroll
        for (int f = 0; f < 4; ++f) {
            float fr = (float)(1 << f);
            #pragma unroll
            for (int dim = 0; dim < 3; ++dim) {
                float ang = dd[dim] * fr;
                bufA[(131 + f * 6 + dim)     * AS + t] = to_tf32(sinf(ang));
                bufA[(131 + f * 6 + 3 + dim) * AS + t] = to_tf32(cosf(ang));
            }
        }
        #pragma unroll
        for (int r = 155; r < 160; ++r) bufA[r * AS + t] = 0.f;
    }

    layer_mma<160, 64, true >(Wv, 155, 155, bv,       bufA, bufB, wbuf, t);  // h

    // rgb = Wr @ h + br  -> out layout: [alpha(N)][r(N)][g(N)][b(N)]
    if (t < TILE) {
        float s0 = __ldg(br), s1 = __ldg(br + 1), s2 = __ldg(br + 2);
        #pragma unroll 4
        for (int i = 0; i < 64; ++i) {
            float h = bufB[i * AS + t];
            s0 += __ldg(Wr + i)       * h;
            s1 += __ldg(Wr + 64 + i)  * h;
            s2 += __ldg(Wr + 128 + i) * h;
        }
        int n = tile0 + t;
        out[NPTS + n]            = s0;
        out[NPTS + NPTS + n]     = s1;
        out[NPTS + 2 * NPTS + n] = s2;
    }
}

// ---------------------------------------------------------------------------
extern "C" void kernel_launch(void* const* d_in, const int* in_sizes, int n_in,
                              void* d_out, int out_size) {
    const float* part_coord     = (const float*)d_in[0];
    const float* viewdir        = (const float*)d_in[1];
    const float* part_bounds    = (const float*)d_in[2];
    const float* part_triplanes = (const float*)d_in[3];
    const float* nf_latent      = (const float*)d_in[4];
    const float* W1 = (const float*)d_in[5];  const float* b1 = (const float*)d_in[6];
    const float* W2 = (const float*)d_in[7];  const float* b2 = (const float*)d_in[8];
    const float* Wa = (const float*)d_in[9];  const float* ba = (const float*)d_in[10];
    const float* Wf = (const float*)d_in[11]; const float* bf = (const float*)d_in[12];
    const float* Wl = (const float*)d_in[13]; const float* bl = (const float*)d_in[14];
    const float* Wv = (const float*)d_in[15]; const float* bv = (const float*)d_in[16];
    const float* Wr = (const float*)d_in[17]; const float* br = (const float*)d_in[18];
    const int* part_idx = (const int*)d_in[19];
    const int* ind      = (const int*)d_in[20];
    float* out = (float*)d_out;

    transpose_planes<<<dim3(RR, NPART * 3), THREADS>>>(part_triplanes);
    prep_bleff<<<1, 128>>>(Wl, bl, nf_latent, ind);

    const size_t SMEM = (size_t)(160 * AS + 128 * AS + 128 * 136) * 4;  // 226304 B
    (void)cudaFuncSetAttribute(tpose_kernel,
                               cudaFuncAttributeMaxDynamicSharedMemorySize, (int)SMEM);
    tpose_kernel<<<NPTS / TILE, THREADS, SMEM>>>(
        part_coord, viewdir, part_bounds,
        W1, b1, W2, b2, Wa, ba, Wf, bf, Wl, Wv, bv, Wr, br,
        part_idx, out);
}

// round 6
// speedup vs baseline: 2.0032x; 1.2766x over previous
#include <cuda_runtime.h>
#include <math.h>
#include <stdint.h>

#define NPTS   262144
#define NPART  24
#define CC     24
#define RR     128
#define TILE   128
#define THREADS 256
#define AS     136     // activation smem stride: 136 % 32 == 8 -> B-operand conflict-free

// Channel-last triplanes: [p][k][y][x][c], 24*3*128*128*24 floats = 113 MB
__device__ float g_planes[(size_t)NPART * 3 * RR * RR * CC];
__device__ float g_bl_eff[128];
// tf32-rounded, padded weights (prepass output)
__device__ float g_W1[128 * 72];
__device__ float g_W2[128 * 128];
__device__ float g_Wf[128 * 128];
__device__ float g_Wl[128 * 128];   // first 128 cols only (latent folded into bias)
__device__ float g_Wv[64 * 160];    // padded 155 -> 160 with zeros

__device__ __forceinline__ float to_tf32(float x) {
    uint32_t y;
    asm("cvt.rna.tf32.f32 %0, %1;" : "=r"(y) : "f"(x));
    return __uint_as_float(y);
}

__device__ __forceinline__ void cp16(float* dst, const float* src) {
    uint32_t d = (uint32_t)__cvta_generic_to_shared(dst);
    asm volatile("cp.async.ca.shared.global [%0], [%1], 16;" :: "r"(d), "l"(src));
}

// ---------------------------------------------------------------------------
// Prepass: blockIdx.y < 72 -> triplane transpose; blockIdx.y == 72 -> weight
// tf32 conversion + bl_eff (latent fold). One launch.
// ---------------------------------------------------------------------------
__global__ void prepass(const float* __restrict__ tp,
                        const float* __restrict__ W1, const float* __restrict__ W2,
                        const float* __restrict__ Wf, const float* __restrict__ Wl,
                        const float* __restrict__ Wv,
                        const float* __restrict__ bl,
                        const float* __restrict__ nf_latent,
                        const int* __restrict__ ind) {
    int t = threadIdx.x;
    if (blockIdx.y == NPART * 3) {
        int g = blockIdx.x * THREADS + t;          // 0 .. 32767
        const int STR = RR * THREADS;              // 32768
        for (int i = g; i < 128 * 72;  i += STR) g_W1[i] = to_tf32(W1[i]);
        for (int i = g; i < 128 * 128; i += STR) g_W2[i] = to_tf32(W2[i]);
        for (int i = g; i < 128 * 128; i += STR) g_Wf[i] = to_tf32(Wf[i]);
        for (int i = g; i < 128 * 128; i += STR) {
            int j = i >> 7, c = i & 127;
            g_Wl[i] = to_tf32(Wl[j * 256 + c]);
        }
        for (int i = g; i < 64 * 160; i += STR) {
            int j = i / 160, c = i - j * 160;
            g_Wv[i] = (c < 155) ? to_tf32(Wv[j * 155 + c]) : 0.f;
        }
        if (blockIdx.x == 0 && t < 128) {
            const float* L = nf_latent + (size_t)ind[0] * 128;
            float s = bl[t];
            #pragma unroll 4
            for (int l = 0; l < 128; ++l) s += Wl[t * 256 + 128 + l] * L[l];
            g_bl_eff[t] = s;
        }
        return;
    }

    __shared__ float tile[CC][136];
    int y  = blockIdx.x;
    int pk = blockIdx.y;
    int p = pk / 3, k = pk % 3;
    for (int it = t; it < CC * RR; it += THREADS) {
        int c = it >> 7;
        int x = it & 127;
        tile[c][x] = tp[(((size_t)(p * 72 + k * 24 + c) * RR + y) * RR) + x];
    }
    __syncthreads();
    float* dst = g_planes + (((size_t)(p * 3 + k) * RR + y) * RR) * CC;
    for (int it = t; it < CC * RR; it += THREADS) {
        int x = it / 24;
        int c = it - x * 24;
        dst[it] = tile[c][x];
    }
}

// ---------------------------------------------------------------------------
// tf32 tensor-core layer: actout[OUT][128] = act(W @ actin[KDIM][128] + bias)
// Weights pre-rounded in gW ([OUT][KDIM] row-major); staged via cp.async into
// wbuf [OUT][KDIM+4] (WS%32==4 -> A-operand conflict-free).
// mma.m16n8k8, warp tile = (OUT/4) x 64.
// ---------------------------------------------------------------------------
template<int KDIM, int OUT, bool RELU, bool ROUND_OUT>
__device__ __forceinline__ void layer_mma(const float* __restrict__ gW,
                                          const float* __restrict__ bias,
                                          const float* actin, float* actout,
                                          float* wbuf, int t) {
    constexpr int WS = KDIM + 4;     // 76 / 132 / 164 : all ≡ 4 or 12 (mod 32)
    constexpr int K4 = KDIM / 4;
    for (int ch = t; ch < OUT * K4; ch += THREADS) {
        int j = ch / K4;
        int c = ch - j * K4;
        cp16(wbuf + j * WS + c * 4, gW + j * KDIM + c * 4);
    }
    asm volatile("cp.async.commit_group;\ncp.async.wait_group 0;" ::: "memory");
    __syncthreads();

    const int lane = t & 31;
    const int wid  = t >> 5;
    const int arow = lane >> 2;   // 0..7
    const int acol = lane & 3;    // 0..3
    constexpr int MT = OUT / 64;  // 2 for OUT=128, 1 for OUT=64
    const int Mbase = (wid & 3) * (MT * 16);
    const int Nbase = (wid >> 2) * 64;

    float c[MT][8][4];
    #pragma unroll
    for (int mt = 0; mt < MT; ++mt)
        #pragma unroll
        for (int nt = 0; nt < 8; ++nt)
            #pragma unroll
            for (int u = 0; u < 4; ++u) c[mt][nt][u] = 0.f;

    #pragma unroll 2
    for (int k0 = 0; k0 < KDIM; k0 += 8) {
        uint32_t A[MT][4];
        #pragma unroll
        for (int mt = 0; mt < MT; ++mt) {
            const float* wb = wbuf + (Mbase + mt * 16 + arow) * WS + k0 + acol;
            A[mt][0] = __float_as_uint(wb[0]);
            A[mt][1] = __float_as_uint(wb[8 * WS]);
            A[mt][2] = __float_as_uint(wb[4]);
            A[mt][3] = __float_as_uint(wb[8 * WS + 4]);
        }
        uint32_t B[8][2];
        #pragma unroll
        for (int nt = 0; nt < 8; ++nt) {
            const float* ab = actin + (k0 + acol) * AS + Nbase + nt * 8 + arow;
            B[nt][0] = __float_as_uint(ab[0]);
            B[nt][1] = __float_as_uint(ab[4 * AS]);
        }
        #pragma unroll
        for (int mt = 0; mt < MT; ++mt)
            #pragma unroll
            for (int nt = 0; nt < 8; ++nt) {
                asm volatile(
                    "mma.sync.aligned.m16n8k8.row.col.f32.tf32.tf32.f32 "
                    "{%0,%1,%2,%3}, {%4,%5,%6,%7}, {%8,%9}, {%0,%1,%2,%3};"
                    : "+f"(c[mt][nt][0]), "+f"(c[mt][nt][1]),
                      "+f"(c[mt][nt][2]), "+f"(c[mt][nt][3])
                    : "r"(A[mt][0]), "r"(A[mt][1]), "r"(A[mt][2]), "r"(A[mt][3]),
                      "r"(B[nt][0]), "r"(B[nt][1]));
            }
    }

    #pragma unroll
    for (int mt = 0; mt < MT; ++mt) {
        int m0 = Mbase + mt * 16 + arow;
        float bv0 = __ldg(bias + m0);
        float bv1 = __ldg(bias + m0 + 8);
        #pragma unroll
        for (int nt = 0; nt < 8; ++nt) {
            int n0 = Nbase + nt * 8 + 2 * acol;
            float r0 = c[mt][nt][0] + bv0, r1 = c[mt][nt][1] + bv0;
            float r2 = c[mt][nt][2] + bv1, r3 = c[mt][nt][3] + bv1;
            if (RELU) {
                r0 = fmaxf(r0, 0.f); r1 = fmaxf(r1, 0.f);
                r2 = fmaxf(r2, 0.f); r3 = fmaxf(r3, 0.f);
            }
            if (ROUND_OUT) {
                r0 = to_tf32(r0); r1 = to_tf32(r1);
                r2 = to_tf32(r2); r3 = to_tf32(r3);
            }
            float2 lo = make_float2(r0, r1);
            float2 hi = make_float2(r2, r3);
            *(float2*)(actout + m0 * AS + n0)       = lo;
            *(float2*)(actout + (m0 + 8) * AS + n0) = hi;
        }
    }
    __syncthreads();
}

// ---------------------------------------------------------------------------
// Main fused kernel: one block = 128 points, full pipeline in SMEM.
// ---------------------------------------------------------------------------
__global__ void __launch_bounds__(THREADS, 1)
tpose_kernel(const float* __restrict__ part_coord,
             const float* __restrict__ viewdir,
             const float* __restrict__ part_bounds,
             const float* __restrict__ b1, const float* __restrict__ b2,
             const float* __restrict__ Wa, const float* __restrict__ ba,
             const float* __restrict__ bf,
             const float* __restrict__ bv,
             const float* __restrict__ Wr, const float* __restrict__ br,
             const int* __restrict__ part_idx,
             float* __restrict__ out) {
    extern __shared__ float smem[];
    float* bufA = smem;                    // 160 rows x AS
    float* bufB = bufA + 160 * AS;         // 128 rows x AS
    float* wbuf = bufB + 128 * AS;         // 128*164 max words; sampling scratch overlaid
    int*   sO00 = (int*)wbuf;
    int*   sO01 = sO00 + 3 * TILE;
    int*   sO10 = sO01 + 3 * TILE;
    int*   sO11 = sO10 + 3 * TILE;
    float* sWx  = (float*)(sO11 + 3 * TILE);
    float* sWy  = sWx + 3 * TILE;

    int t = threadIdx.x;
    int tile0 = blockIdx.x * TILE;

    // --- per-point sampling params ---
    if (t < TILE) {
        int n = tile0 + t;
        float P[3] = { part_coord[3*n], part_coord[3*n+1], part_coord[3*n+2] };
        int p = part_idx[n];
        // part_bounds layout (NPART,2,3): [mn_xyz, mx_xyz]
        const float* bb = part_bounds + p * 6;
        float g[3];
        #pragma unroll
        for (int d = 0; d < 3; ++d) {
            float mn = bb[d], mx = bb[3 + d];
            float c = 0.5f * (mn + mx), h = 0.5f * (mx - mn);
            g[d] = (P[d] - c) / h;
        }
        const int ka[3] = {0, 0, 1};
        const int kb[3] = {1, 2, 2};
        #pragma unroll
        for (int k = 0; k < 3; ++k) {
            float u = g[ka[k]], v = g[kb[k]];
            float px = fminf(fmaxf((u + 1.f) * 0.5f * (RR - 1), 0.f), (float)(RR - 1));
            float py = fminf(fmaxf((v + 1.f) * 0.5f * (RR - 1), 0.f), (float)(RR - 1));
            float x0 = floorf(px), y0 = floorf(py);
            int x0i = (int)x0, y0i = (int)y0;
            int x1i = min(x0i + 1, RR - 1), y1i = min(y0i + 1, RR - 1);
            int rb = (p * 3 + k) * RR;
            sO00[k*TILE + t] = ((rb + y0i) * RR + x0i) * CC;
            sO01[k*TILE + t] = ((rb + y0i) * RR + x1i) * CC;
            sO10[k*TILE + t] = ((rb + y1i) * RR + x0i) * CC;
            sO11[k*TILE + t] = ((rb + y1i) * RR + x1i) * CC;
            sWx[k*TILE + t] = px - x0;
            sWy[k*TILE + t] = py - y0;
        }
    }
    __syncthreads();

    // --- triplane gather: lanes 0..23 = channels (contiguous 96B reads) ---
    {
        int w = t >> 5, c = t & 31;
        if (c < CC) {
            for (int idx = w; idx < 3 * TILE; idx += 8) {
                int o00 = sO00[idx], o01 = sO01[idx], o10 = sO10[idx], o11 = sO11[idx];
                float wx = sWx[idx], wy = sWy[idx];
                float f00 = g_planes[o00 + c], f01 = g_planes[o01 + c];
                float f10 = g_planes[o10 + c], f11 = g_planes[o11 + c];
                float f = f00 * (1.f - wx) * (1.f - wy) + f01 * wx * (1.f - wy)
                        + f10 * (1.f - wx) * wy        + f11 * wx * wy;
                int k = idx >> 7, pt = idx & 127;
                bufA[(k * CC + c) * AS + pt] = to_tf32(f);
            }
        }
    }
    __syncthreads();   // gather (reads sO in wbuf) done before layer1 stages wbuf

    layer_mma<72, 128, true,  true >(g_W1, b1,       bufA, bufB, wbuf, t);  // net1
    layer_mma<128,128, true,  true >(g_W2, b2,       bufB, bufA, wbuf, t);  // net2 -> bufA

    // alpha = Wa @ net2 + ba (4 independent chains)
    if (t < TILE) {
        float s0 = 0.f, s1 = 0.f, s2 = 0.f, s3 = 0.f;
        #pragma unroll 4
        for (int i = 0; i < 128; i += 4) {
            s0 += __ldg(Wa + i)     * bufA[i * AS + t];
            s1 += __ldg(Wa + i + 1) * bufA[(i + 1) * AS + t];
            s2 += __ldg(Wa + i + 2) * bufA[(i + 2) * AS + t];
            s3 += __ldg(Wa + i + 3) * bufA[(i + 3) * AS + t];
        }
        out[tile0 + t] = (s0 + s1) + (s2 + s3) + __ldg(ba);
    }

    layer_mma<128,128, false, true >(g_Wf, bf,       bufA, bufB, wbuf, t);  // features1
    layer_mma<128,128, false, true >(g_Wl, g_bl_eff, bufB, bufA, wbuf, t);  // features2 (latent folded)

    // view posenc -> bufA rows 128..154, zero rows 155..159 (K padded to 160)
    if (t < TILE) {
        int n = tile0 + t;
        float dd[3] = { viewdir[3*n], viewdir[3*n+1], viewdir[3*n+2] };
        bufA[128 * AS + t] = to_tf32(dd[0]);
        bufA[129 * AS + t] = to_tf32(dd[1]);
        bufA[130 * AS + t] = to_tf32(dd[2]);
        #pragma unroll
        for (int f = 0; f < 4; ++f) {
            float fr = (float)(1 << f);
            #pragma unroll
            for (int dim = 0; dim < 3; ++dim) {
                float ang = dd[dim] * fr;
                bufA[(131 + f * 6 + dim)     * AS + t] = to_tf32(sinf(ang));
                bufA[(131 + f * 6 + 3 + dim) * AS + t] = to_tf32(cosf(ang));
            }
        }
        #pragma unroll
        for (int r = 155; r < 160; ++r) bufA[r * AS + t] = 0.f;
    }

    layer_mma<160, 64, true,  false>(g_Wv, bv,       bufA, bufB, wbuf, t);  // h (fp32 out)

    // rgb = Wr @ h + br  -> out layout: [alpha(N)][r(N)][g(N)][b(N)]
    if (t < TILE) {
        float s0 = __ldg(br), s1 = __ldg(br + 1), s2 = __ldg(br + 2);
        #pragma unroll 4
        for (int i = 0; i < 64; ++i) {
            float h = bufB[i * AS + t];
            s0 += __ldg(Wr + i)       * h;
            s1 += __ldg(Wr + 64 + i)  * h;
            s2 += __ldg(Wr + 128 + i) * h;
        }
        int n = tile0 + t;
        out[NPTS + n]            = s0;
        out[NPTS + NPTS + n]     = s1;
        out[NPTS + 2 * NPTS + n] = s2;
    }
}

// ---------------------------------------------------------------------------
extern "C" void kernel_launch(void* const* d_in, const int* in_sizes, int n_in,
                              void* d_out, int out_size) {
    const float* part_coord     = (const float*)d_in[0];
    const float* viewdir        = (const float*)d_in[1];
    const float* part_bounds    = (const float*)d_in[2];
    const float* part_triplanes = (const float*)d_in[3];
    const float* nf_latent      = (const float*)d_in[4];
    const float* W1 = (const float*)d_in[5];  const float* b1 = (const float*)d_in[6];
    const float* W2 = (const float*)d_in[7];  const float* b2 = (const float*)d_in[8];
    const float* Wa = (const float*)d_in[9];  const float* ba = (const float*)d_in[10];
    const float* Wf = (const float*)d_in[11]; const float* bf = (const float*)d_in[12];
    const float* Wl = (const float*)d_in[13]; const float* bl = (const float*)d_in[14];
    const float* Wv = (const float*)d_in[15]; const float* bv = (const float*)d_in[16];
    const float* Wr = (const float*)d_in[17]; const float* br = (const float*)d_in[18];
    const int* part_idx = (const int*)d_in[19];
    const int* ind      = (const int*)d_in[20];
    float* out = (float*)d_out;

    prepass<<<dim3(RR, NPART * 3 + 1), THREADS>>>(part_triplanes,
                                                  W1, W2, Wf, Wl, Wv,
                                                  bl, nf_latent, ind);

    const size_t SMEM = (size_t)(160 * AS + 128 * AS + 128 * 164) * 4;  // 240640 B? no:
    // 160*136 + 128*136 + 128*164 = 21760 + 17408 + 20992 = 60160 words -> 240640 B too big?
    // max wbuf actually needed: KDIM=160,OUT=64 -> 64*164 = 10496; KDIM=128,OUT=128 -> 128*132 = 16896.
    const size_t SMEM2 = (size_t)(160 * AS + 128 * AS + 16896) * 4;     // 224256 B
    (void)cudaFuncSetAttribute(tpose_kernel,
                               cudaFuncAttributeMaxDynamicSharedMemorySize, (int)SMEM2);
    tpose_kernel<<<NPTS / TILE, THREADS, SMEM2>>>(
        part_coord, viewdir, part_bounds,
        b1, b2, Wa, ba, bf, bv, Wr, br,
        part_idx, out);
    (void)SMEM;
}

// round 7
// speedup vs baseline: 2.4570x; 1.2265x over previous
#include <cuda_runtime.h>
#include <math.h>
#include <stdint.h>

#define NPTS   262144
#define NPART  24
#define CC     24
#define RR     128
#define TILE   128
#define THREADS 512
#define AS     136     // activation smem stride: 136 % 32 == 8 -> B-operand conflict-free

// Channel-last triplanes: [p][k][y][x][c], 24*3*128*128*24 floats = 113 MB
__device__ float g_planes[(size_t)NPART * 3 * RR * RR * CC];
__device__ float g_bl_eff[128];
// tf32-rounded, padded weights (prepass output)
__device__ float g_W1[128 * 72];
__device__ float g_W2[128 * 128];
__device__ float g_Wf[128 * 128];
__device__ float g_Wl[128 * 128];   // first 128 cols only (latent folded into bias)
__device__ float g_Wv[64 * 160];    // padded 155 -> 160 with zeros

__device__ __forceinline__ float to_tf32(float x) {
    uint32_t y;
    asm("cvt.rna.tf32.f32 %0, %1;" : "=r"(y) : "f"(x));
    return __uint_as_float(y);
}

__device__ __forceinline__ void cp16(float* dst, const float* src) {
    uint32_t d = (uint32_t)__cvta_generic_to_shared(dst);
    asm volatile("cp.async.ca.shared.global [%0], [%1], 16;" :: "r"(d), "l"(src));
}

// ---------------------------------------------------------------------------
// Prepass: blockIdx.y < 72 -> triplane transpose; blockIdx.y == 72 -> weight
// tf32 conversion + bl_eff (latent fold). One launch.
// ---------------------------------------------------------------------------
__global__ void prepass(const float* __restrict__ tp,
                        const float* __restrict__ W1, const float* __restrict__ W2,
                        const float* __restrict__ Wf, const float* __restrict__ Wl,
                        const float* __restrict__ Wv,
                        const float* __restrict__ bl,
                        const float* __restrict__ nf_latent,
                        const int* __restrict__ ind) {
    int t = threadIdx.x;
    if (blockIdx.y == NPART * 3) {
        int g = blockIdx.x * THREADS + t;
        const int STR = RR * THREADS;
        for (int i = g; i < 128 * 72;  i += STR) g_W1[i] = to_tf32(W1[i]);
        for (int i = g; i < 128 * 128; i += STR) g_W2[i] = to_tf32(W2[i]);
        for (int i = g; i < 128 * 128; i += STR) g_Wf[i] = to_tf32(Wf[i]);
        for (int i = g; i < 128 * 128; i += STR) {
            int j = i >> 7, c = i & 127;
            g_Wl[i] = to_tf32(Wl[j * 256 + c]);
        }
        for (int i = g; i < 64 * 160; i += STR) {
            int j = i / 160, c = i - j * 160;
            g_Wv[i] = (c < 155) ? to_tf32(Wv[j * 155 + c]) : 0.f;
        }
        if (blockIdx.x == 0 && t < 128) {
            const float* L = nf_latent + (size_t)ind[0] * 128;
            float s = bl[t];
            #pragma unroll 4
            for (int l = 0; l < 128; ++l) s += Wl[t * 256 + 128 + l] * L[l];
            g_bl_eff[t] = s;
        }
        return;
    }

    __shared__ float tile[CC][136];
    int y  = blockIdx.x;
    int pk = blockIdx.y;
    int p = pk / 3, k = pk % 3;
    for (int it = t; it < CC * RR; it += THREADS) {
        int c = it >> 7;
        int x = it & 127;
        tile[c][x] = tp[(((size_t)(p * 72 + k * 24 + c) * RR + y) * RR) + x];
    }
    __syncthreads();
    float* dst = g_planes + (((size_t)(p * 3 + k) * RR + y) * RR) * CC;
    for (int it = t; it < CC * RR; it += THREADS) {
        int x = it / 24;
        int c = it - x * 24;
        dst[it] = tile[c][x];
    }
}

// ---------------------------------------------------------------------------
// tf32 tensor-core layer: actout[OUT][128] = act(W @ actin[KDIM][128] + bias)
// 16 warps, warp tile 32(M) x 32(N): MGROUPS = OUT/32, NGROUPS = 4.
// Weights pre-rounded in gW; staged via cp.async into wbuf [OUT][KDIM+4]
// (WS%32 in {4,12} -> A-operand conflict-free; AS%32==8 -> B conflict-free).
// ---------------------------------------------------------------------------
template<int KDIM, int OUT, bool RELU, bool ROUND_OUT>
__device__ __forceinline__ void layer_mma(const float* __restrict__ gW,
                                          const float* __restrict__ bias,
                                          const float* actin, float* actout,
                                          float* wbuf, int t) {
    constexpr int WS = KDIM + 4;     // 76 / 132 / 164
    constexpr int K4 = KDIM / 4;
    for (int ch = t; ch < OUT * K4; ch += THREADS) {
        int j = ch / K4;
        int c = ch - j * K4;
        cp16(wbuf + j * WS + c * 4, gW + j * KDIM + c * 4);
    }
    asm volatile("cp.async.commit_group;\ncp.async.wait_group 0;" ::: "memory");
    __syncthreads();

    const int lane = t & 31;
    const int wid  = t >> 5;
    const int arow = lane >> 2;   // 0..7
    const int acol = lane & 3;    // 0..3
    constexpr int MG = OUT / 32;  // 4 (OUT=128) or 2 (OUT=64)
    const int mg = wid & (MG - 1);
    const int ng = wid / MG;      // 0..3 active
    const bool active = (ng < 4);
    const int Mbase = mg * 32;
    const int Nbase = ng * 32;

    float c[2][4][4];
    #pragma unroll
    for (int mt = 0; mt < 2; ++mt)
        #pragma unroll
        for (int nt = 0; nt < 4; ++nt)
            #pragma unroll
            for (int u = 0; u < 4; ++u) c[mt][nt][u] = 0.f;

    if (active) {
        #pragma unroll 2
        for (int k0 = 0; k0 < KDIM; k0 += 8) {
            uint32_t A[2][4];
            #pragma unroll
            for (int mt = 0; mt < 2; ++mt) {
                const float* wb = wbuf + (Mbase + mt * 16 + arow) * WS + k0 + acol;
                A[mt][0] = __float_as_uint(wb[0]);
                A[mt][1] = __float_as_uint(wb[8 * WS]);
                A[mt][2] = __float_as_uint(wb[4]);
                A[mt][3] = __float_as_uint(wb[8 * WS + 4]);
            }
            uint32_t B[4][2];
            #pragma unroll
            for (int nt = 0; nt < 4; ++nt) {
                const float* ab = actin + (k0 + acol) * AS + Nbase + nt * 8 + arow;
                B[nt][0] = __float_as_uint(ab[0]);
                B[nt][1] = __float_as_uint(ab[4 * AS]);
            }
            #pragma unroll
            for (int mt = 0; mt < 2; ++mt)
                #pragma unroll
                for (int nt = 0; nt < 4; ++nt) {
                    asm volatile(
                        "mma.sync.aligned.m16n8k8.row.col.f32.tf32.tf32.f32 "
                        "{%0,%1,%2,%3}, {%4,%5,%6,%7}, {%8,%9}, {%0,%1,%2,%3};"
                        : "+f"(c[mt][nt][0]), "+f"(c[mt][nt][1]),
                          "+f"(c[mt][nt][2]), "+f"(c[mt][nt][3])
                        : "r"(A[mt][0]), "r"(A[mt][1]), "r"(A[mt][2]), "r"(A[mt][3]),
                          "r"(B[nt][0]), "r"(B[nt][1]));
                }
        }

        #pragma unroll
        for (int mt = 0; mt < 2; ++mt) {
            int m0 = Mbase + mt * 16 + arow;
            float bv0 = __ldg(bias + m0);
            float bv1 = __ldg(bias + m0 + 8);
            #pragma unroll
            for (int nt = 0; nt < 4; ++nt) {
                int n0 = Nbase + nt * 8 + 2 * acol;
                float r0 = c[mt][nt][0] + bv0, r1 = c[mt][nt][1] + bv0;
                float r2 = c[mt][nt][2] + bv1, r3 = c[mt][nt][3] + bv1;
                if (RELU) {
                    r0 = fmaxf(r0, 0.f); r1 = fmaxf(r1, 0.f);
                    r2 = fmaxf(r2, 0.f); r3 = fmaxf(r3, 0.f);
                }
                if (ROUND_OUT) {
                    r0 = to_tf32(r0); r1 = to_tf32(r1);
                    r2 = to_tf32(r2); r3 = to_tf32(r3);
                }
                *(float2*)(actout + m0 * AS + n0)       = make_float2(r0, r1);
                *(float2*)(actout + (m0 + 8) * AS + n0) = make_float2(r2, r3);
            }
        }
    }
    __syncthreads();
}

// ---------------------------------------------------------------------------
// Main fused kernel: one block = 128 points, full pipeline in SMEM.
// ---------------------------------------------------------------------------
__global__ void __launch_bounds__(THREADS, 1)
tpose_kernel(const float* __restrict__ part_coord,
             const float* __restrict__ viewdir,
             const float* __restrict__ part_bounds,
             const float* __restrict__ b1, const float* __restrict__ b2,
             const float* __restrict__ Wa, const float* __restrict__ ba,
             const float* __restrict__ bf,
             const float* __restrict__ bv,
             const float* __restrict__ Wr, const float* __restrict__ br,
             const int* __restrict__ part_idx,
             float* __restrict__ out) {
    extern __shared__ float smem[];
    float* bufA = smem;                    // 160 rows x AS
    float* bufB = bufA + 160 * AS;         // 128 rows x AS
    float* wbuf = bufB + 128 * AS;         // 16896 words max; sampling scratch overlaid
    int*   sO00 = (int*)wbuf;
    int*   sO01 = sO00 + 3 * TILE;
    int*   sO10 = sO01 + 3 * TILE;
    int*   sO11 = sO10 + 3 * TILE;
    float* sWx  = (float*)(sO11 + 3 * TILE);
    float* sWy  = sWx + 3 * TILE;

    int t = threadIdx.x;
    int tile0 = blockIdx.x * TILE;

    // --- per-point sampling params: one thread per (plane k, point) ---
    if (t < 3 * TILE) {
        int pt = t & 127;
        int k  = t >> 7;                   // 0..2
        int n  = tile0 + pt;
        float P[3] = { part_coord[3*n], part_coord[3*n+1], part_coord[3*n+2] };
        int p = part_idx[n];
        // part_bounds layout (NPART,2,3): [mn_xyz, mx_xyz]
        const float* bb = part_bounds + p * 6;
        const int ka[3] = {0, 0, 1};
        const int kb[3] = {1, 2, 2};
        int da = ka[k], db = kb[k];
        float mnU = bb[da], mxU = bb[3 + da];
        float mnV = bb[db], mxV = bb[3 + db];
        float u = (P[da] - 0.5f * (mnU + mxU)) / (0.5f * (mxU - mnU));
        float v = (P[db] - 0.5f * (mnV + mxV)) / (0.5f * (mxV - mnV));
        float px = fminf(fmaxf((u + 1.f) * 0.5f * (RR - 1), 0.f), (float)(RR - 1));
        float py = fminf(fmaxf((v + 1.f) * 0.5f * (RR - 1), 0.f), (float)(RR - 1));
        float x0 = floorf(px), y0 = floorf(py);
        int x0i = (int)x0, y0i = (int)y0;
        int x1i = min(x0i + 1, RR - 1), y1i = min(y0i + 1, RR - 1);
        int rb = (p * 3 + k) * RR;
        sO00[t] = ((rb + y0i) * RR + x0i) * CC;
        sO01[t] = ((rb + y0i) * RR + x1i) * CC;
        sO10[t] = ((rb + y1i) * RR + x0i) * CC;
        sO11[t] = ((rb + y1i) * RR + x1i) * CC;
        sWx[t]  = px - x0;
        sWy[t]  = py - y0;
    }
    __syncthreads();

    // --- triplane gather: lanes 0..23 = channels (contiguous 96B reads) ---
    {
        int w = t >> 5, c = t & 31;        // 16 warps
        if (c < CC) {
            for (int idx = w; idx < 3 * TILE; idx += 16) {
                int o00 = sO00[idx], o01 = sO01[idx], o10 = sO10[idx], o11 = sO11[idx];
                float wx = sWx[idx], wy = sWy[idx];
                float f00 = g_planes[o00 + c], f01 = g_planes[o01 + c];
                float f10 = g_planes[o10 + c], f11 = g_planes[o11 + c];
                float f = f00 * (1.f - wx) * (1.f - wy) + f01 * wx * (1.f - wy)
                        + f10 * (1.f - wx) * wy        + f11 * wx * wy;
                int k = idx >> 7, pt = idx & 127;
                bufA[(k * CC + c) * AS + pt] = to_tf32(f);
            }
        }
    }
    __syncthreads();   // gather (reads sO in wbuf) done before layer1 stages wbuf

    layer_mma<72, 128, true,  true >(g_W1, b1,       bufA, bufB, wbuf, t);  // net1
    layer_mma<128,128, true,  true >(g_W2, b2,       bufB, bufA, wbuf, t);  // net2 -> bufA

    // alpha = Wa @ net2 + ba (4 independent chains)
    if (t < TILE) {
        float s0 = 0.f, s1 = 0.f, s2 = 0.f, s3 = 0.f;
        #pragma unroll 4
        for (int i = 0; i < 128; i += 4) {
            s0 += __ldg(Wa + i)     * bufA[i * AS + t];
            s1 += __ldg(Wa + i + 1) * bufA[(i + 1) * AS + t];
            s2 += __ldg(Wa + i + 2) * bufA[(i + 2) * AS + t];
            s3 += __ldg(Wa + i + 3) * bufA[(i + 3) * AS + t];
        }
        out[tile0 + t] = (s0 + s1) + (s2 + s3) + __ldg(ba);
    }

    layer_mma<128,128, false, true >(g_Wf, bf,       bufA, bufB, wbuf, t);  // features1
    layer_mma<128,128, false, true >(g_Wl, g_bl_eff, bufB, bufA, wbuf, t);  // features2 (latent folded)

    // view posenc -> bufA rows 128..154, zero rows 155..159 (K padded to 160)
    if (t < TILE) {
        int n = tile0 + t;
        float dd[3] = { viewdir[3*n], viewdir[3*n+1], viewdir[3*n+2] };
        bufA[128 * AS + t] = to_tf32(dd[0]);
        bufA[129 * AS + t] = to_tf32(dd[1]);
        bufA[130 * AS + t] = to_tf32(dd[2]);
        #pragma unroll
        for (int f = 0; f < 4; ++f) {
            float fr = (float)(1 << f);
            #pragma unroll
            for (int dim = 0; dim < 3; ++dim) {
                float sv, cv;
                __sincosf(dd[dim] * fr, &sv, &cv);
                bufA[(131 + f * 6 + dim)     * AS + t] = to_tf32(sv);
                bufA[(131 + f * 6 + 3 + dim) * AS + t] = to_tf32(cv);
            }
        }
        #pragma unroll
        for (int r = 155; r < 160; ++r) bufA[r * AS + t] = 0.f;
    }

    layer_mma<160, 64, true,  false>(g_Wv, bv,       bufA, bufB, wbuf, t);  // h (fp32 out)

    // rgb = Wr @ h + br  -> out layout: [alpha(N)][r(N)][g(N)][b(N)]
    if (t < TILE) {
        float s0 = __ldg(br), s1 = __ldg(br + 1), s2 = __ldg(br + 2);
        #pragma unroll 4
        for (int i = 0; i < 64; ++i) {
            float h = bufB[i * AS + t];
            s0 += __ldg(Wr + i)       * h;
            s1 += __ldg(Wr + 64 + i)  * h;
            s2 += __ldg(Wr + 128 + i) * h;
        }
        int n = tile0 + t;
        out[NPTS + n]            = s0;
        out[NPTS + NPTS + n]     = s1;
        out[NPTS + 2 * NPTS + n] = s2;
    }
}

// ---------------------------------------------------------------------------
extern "C" void kernel_launch(void* const* d_in, const int* in_sizes, int n_in,
                              void* d_out, int out_size) {
    const float* part_coord     = (const float*)d_in[0];
    const float* viewdir        = (const float*)d_in[1];
    const float* part_bounds    = (const float*)d_in[2];
    const float* part_triplanes = (const float*)d_in[3];
    const float* nf_latent      = (const float*)d_in[4];
    const float* W1 = (const float*)d_in[5];  const float* b1 = (const float*)d_in[6];
    const float* W2 = (const float*)d_in[7];  const float* b2 = (const float*)d_in[8];
    const float* Wa = (const float*)d_in[9];  const float* ba = (const float*)d_in[10];
    const float* Wf = (const float*)d_in[11]; const float* bf = (const float*)d_in[12];
    const float* Wl = (const float*)d_in[13]; const float* bl = (const float*)d_in[14];
    const float* Wv = (const float*)d_in[15]; const float* bv = (const float*)d_in[16];
    const float* Wr = (const float*)d_in[17]; const float* br = (const float*)d_in[18];
    const int* part_idx = (const int*)d_in[19];
    const int* ind      = (const int*)d_in[20];
    float* out = (float*)d_out;

    prepass<<<dim3(RR, NPART * 3 + 1), THREADS>>>(part_triplanes,
                                                  W1, W2, Wf, Wl, Wv,
                                                  bl, nf_latent, ind);

    // bufA 160*136 + bufB 128*136 + wbuf 128*132 = 56064 words = 224256 B
    const size_t SMEM = (size_t)(160 * AS + 128 * AS + 16896) * 4;
    (void)cudaFuncSetAttribute(tpose_kernel,
                               cudaFuncAttributeMaxDynamicSharedMemorySize, (int)SMEM);
    tpose_kernel<<<NPTS / TILE, THREADS, SMEM>>>(
        part_coord, viewdir, part_bounds,
        b1, b2, Wa, ba, bf, bv, Wr, br,
        part_idx, out);
}